// round 7
// baseline (speedup 1.0000x reference)
#include <cuda_runtime.h>
#include <cstdint>

#define N_NODES 100000
#define N_EDGES 500000
#define HIDDEN 32
#define HEADS 4
#define PROJ 128
#define LN_EPS 1e-5f

// Per-node accumulator: [node][head][{Sx,Sy,Sz,T}] = 16 floats. 6.4 MB, L2-hot.
// Invariant: zero at entry of every kernel_launch (zeroed at module load;
// node_kernel re-zeroes after reading).
__device__ float g_acc[(size_t)N_NODES * 16];
__device__ int   g_idx64;            // 1 if edge_index is int64
__device__ float g_PJ[HIDDEN * 16];  // folded Wv@Wout (+bv@Wout): [j][h*4+{x,y,z,T}]
__device__ float g_score[HEADS * 13];// per head: M[9] row-major, L[3], C

// ---------------------------------------------------------------------------
// Setup: dtype sniff + folded coefficient tables. One block, 640 threads.
//  tid 0        : sniff (int64 iff first 64 odd 32-bit words are all zero)
//  tid < 512    : PJ[j][k], j=tid>>4, k=tid&15 (h=k>>2, comp=k&3), 32-red each
//  tid 512..595 : score coefficients (36 M, 12 L, 4 C), 32-red each
// ---------------------------------------------------------------------------
__global__ __launch_bounds__(640) void setup_kernel(
    const int* __restrict__ e32,
    const float* __restrict__ Wq, const float* __restrict__ bq,
    const float* __restrict__ Wk, const float* __restrict__ bk,
    const float* __restrict__ Wv, const float* __restrict__ bv,
    const float* __restrict__ Wout)
{
    const int tid = threadIdx.x;
    if (tid == 0) {
        int all_zero = 1;
        for (int i = 0; i < 64; i++)
            if (e32[2 * i + 1] != 0) { all_zero = 0; break; }
        g_idx64 = all_zero;
    }
    if (tid < 512) {
        const int j = tid >> 4, k = tid & 15, h = k >> 2, comp = k & 3;
        float s = 0.f;
#pragma unroll 4
        for (int d = 0; d < 32; d++) {
            const int c = h * 32 + d;
            const float w = Wout[c * HIDDEN + j];
            const float a = (comp < 3) ? Wv[comp * PROJ + c] : bv[c];
            s = fmaf(a, w, s);
        }
        g_PJ[j * 16 + k] = s;
    } else if (tid < 512 + 84) {
        const int u = tid - 512;
        if (u < 36) {                       // M[h][i][jj]
            const int h = u / 9, ij = u % 9, i = ij / 3, jj = ij % 3;
            float s = 0.f;
            for (int d = 0; d < 32; d++) {
                const int c = h * 32 + d;
                s = fmaf(Wq[i * PROJ + c], Wk[jj * PROJ + c], s);
            }
            g_score[h * 13 + ij] = s;
        } else if (u < 48) {                // L[h][i]
            const int t = u - 36, h = t / 3, i = t % 3;
            float s = 0.f;
            for (int d = 0; d < 32; d++) {
                const int c = h * 32 + d;
                s += Wq[i * PROJ + c] * bk[c] + bq[c] * Wk[i * PROJ + c];
            }
            g_score[h * 13 + 9 + i] = s;
        } else if (u < 52) {                // C[h]
            const int h = u - 48;
            float s = 0.f;
            for (int d = 0; d < 32; d++) {
                const int c = h * 32 + d;
                s = fmaf(bq[c], bk[c], s);
            }
            g_score[h * 13 + 12] = s;
        }
    }
}

// ---------------------------------------------------------------------------
// Edge kernel: TWO edges per thread for MLP. Quadratic-form scores, 4-way
// softmax in registers, 4x red.v4.f32 (16 floats) per edge.
// ---------------------------------------------------------------------------
__device__ __forceinline__ void edge_compute(
    const float* __restrict__ sc,
    float rx, float ry, float rz, int col)
{
    float s[HEADS];
#pragma unroll
    for (int h = 0; h < HEADS; h++) {
        const float* m = &sc[h * 13];
        const float tx = fmaf(m[0], rx, fmaf(m[1], ry, m[2] * rz));
        const float ty = fmaf(m[3], rx, fmaf(m[4], ry, m[5] * rz));
        const float tz = fmaf(m[6], rx, fmaf(m[7], ry, m[8] * rz));
        float v = fmaf(rx, tx, fmaf(ry, ty, rz * tz));
        v += fmaf(m[9], rx, fmaf(m[10], ry, fmaf(m[11], rz, m[12])));
        s[h] = v * 0.17677669529663687f;   // 1/sqrt(32)
    }
    const float mx = fmaxf(fmaxf(s[0], s[1]), fmaxf(s[2], s[3]));
    float ex[HEADS], tot = 0.f;
#pragma unroll
    for (int h = 0; h < HEADS; h++) { ex[h] = __expf(s[h] - mx); tot += ex[h]; }
    const float inv = 1.f / tot;

    float* dst = g_acc + (size_t)col * 16;
#pragma unroll
    for (int h = 0; h < HEADS; h++) {
        const float a = ex[h] * inv;
        asm volatile("red.global.add.v4.f32 [%0], {%1,%2,%3,%4};"
                     :: "l"(dst + h * 4), "f"(a * rx), "f"(a * ry), "f"(a * rz), "f"(a)
                     : "memory");
    }
}

__global__ __launch_bounds__(256) void edge_kernel(
    const float* __restrict__ pos, const void* __restrict__ eidx_raw)
{
    __shared__ float sc[HEADS * 13];
    const int tid = threadIdx.x;
    if (tid < HEADS * 13) sc[tid] = g_score[tid];
    __syncthreads();

    const int t = blockIdx.x * 256 + tid;
    const int e0 = 2 * t, e1 = 2 * t + 1;
    if (e0 >= N_EDGES) return;          // N_EDGES even -> e1 valid iff e0 is

    int row0, col0, row1, col1;
    if (g_idx64) {
        const long long* p = (const long long*)eidx_raw;
        row0 = (int)p[e0];           row1 = (int)p[e1];
        col0 = (int)p[N_EDGES + e0]; col1 = (int)p[N_EDGES + e1];
    } else {
        const int* p = (const int*)eidx_raw;
        row0 = p[e0];           row1 = p[e1];
        col0 = p[N_EDGES + e0]; col1 = p[N_EDGES + e1];
    }
    const bool ok0 = (unsigned)row0 < N_NODES && (unsigned)col0 < N_NODES;
    const bool ok1 = (unsigned)row1 < N_NODES && (unsigned)col1 < N_NODES;

    float rx0 = 0.f, ry0 = 0.f, rz0 = 0.f, rx1 = 0.f, ry1 = 0.f, rz1 = 0.f;
    if (ok0) {
        rx0 = pos[row0 * 3 + 0] - pos[col0 * 3 + 0];
        ry0 = pos[row0 * 3 + 1] - pos[col0 * 3 + 1];
        rz0 = pos[row0 * 3 + 2] - pos[col0 * 3 + 2];
    }
    if (ok1) {
        rx1 = pos[row1 * 3 + 0] - pos[col1 * 3 + 0];
        ry1 = pos[row1 * 3 + 1] - pos[col1 * 3 + 1];
        rz1 = pos[row1 * 3 + 2] - pos[col1 * 3 + 2];
    }
    if (ok0) edge_compute(sc, rx0, ry0, rz0, col0);
    if (ok1) edge_compute(sc, rx1, ry1, rz1, col1);
}

// ---------------------------------------------------------------------------
// Node kernel: one THREAD per node. 16-float load, 32 outputs via folded
// tables, in-register LayerNorm + SiLU. Re-zeroes g_acc for the next launch.
// ---------------------------------------------------------------------------
__global__ __launch_bounds__(256) void node_kernel(
    const float* __restrict__ bout, const float* __restrict__ gamma,
    const float* __restrict__ beta, float* __restrict__ out)
{
    __shared__ float sPJ[HIDDEN * 16];
    __shared__ float sb[HIDDEN], sg[HIDDEN], sbt[HIDDEN];
    const int tid = threadIdx.x;
    for (int i = tid; i < HIDDEN * 16; i += 256) sPJ[i] = g_PJ[i];
    if (tid < HIDDEN) { sb[tid] = bout[tid]; sg[tid] = gamma[tid]; sbt[tid] = beta[tid]; }
    __syncthreads();

    const int node = blockIdx.x * 256 + tid;
    if (node >= N_NODES) return;

    float4* ap = reinterpret_cast<float4*>(g_acc + (size_t)node * 16);
    const float4 a0 = ap[0], a1 = ap[1], a2 = ap[2], a3 = ap[3];
    const float4 z = make_float4(0.f, 0.f, 0.f, 0.f);
    ap[0] = z; ap[1] = z; ap[2] = z; ap[3] = z;   // restore zero-invariant

    const float cnt = a0.w + a1.w + a2.w + a3.w;
    const float inv = 1.f / fmaxf(cnt, 1.f);

    float o[HIDDEN];
    float sum = 0.f;
#pragma unroll
    for (int j = 0; j < HIDDEN; j++) {
        const float4* p = reinterpret_cast<const float4*>(&sPJ[j * 16]);
        const float4 p0 = p[0], p1 = p[1], p2 = p[2], p3 = p[3];
        float d = a0.x * p0.x + a0.y * p0.y + a0.z * p0.z + a0.w * p0.w;
        d += a1.x * p1.x + a1.y * p1.y + a1.z * p1.z + a1.w * p1.w;
        d += a2.x * p2.x + a2.y * p2.y + a2.z * p2.z + a2.w * p2.w;
        d += a3.x * p3.x + a3.y * p3.y + a3.z * p3.z + a3.w * p3.w;
        o[j] = fmaf(d, inv, sb[j]);
        sum += o[j];
    }
    const float mu = sum * (1.f / 32.f);
    float sq = 0.f;
#pragma unroll
    for (int j = 0; j < HIDDEN; j++) { const float d = o[j] - mu; sq += d * d; }
    const float rstd = rsqrtf(sq * (1.f / 32.f) + LN_EPS);

    float4 w[8];
#pragma unroll
    for (int j = 0; j < HIDDEN; j++) {
        const float y = (o[j] - mu) * rstd * sg[j] + sbt[j];
        reinterpret_cast<float*>(w)[j] = y / (1.f + __expf(-y));
    }
    float4* op = reinterpret_cast<float4*>(out + (size_t)node * HIDDEN);
#pragma unroll
    for (int k = 0; k < 8; k++) op[k] = w[k];
}

// ---------------------------------------------------------------------------
extern "C" void kernel_launch(void* const* d_in, const int* in_sizes, int n_in,
                              void* d_out, int out_size)
{
    const float* pos   = (const float*)d_in[0];
    const void*  eidx  = d_in[1];
    const float* Wq    = (const float*)d_in[2];
    const float* bq    = (const float*)d_in[3];
    const float* Wk    = (const float*)d_in[4];
    const float* bk    = (const float*)d_in[5];
    const float* Wv    = (const float*)d_in[6];
    const float* bv    = (const float*)d_in[7];
    const float* Wout  = (const float*)d_in[8];
    const float* bout  = (const float*)d_in[9];
    const float* gamma = (const float*)d_in[10];
    const float* beta  = (const float*)d_in[11];
    float*       out   = (float*)d_out;

    setup_kernel<<<1, 640>>>((const int*)eidx, Wq, bq, Wk, bk, Wv, bv, Wout);
    edge_kernel<<<(N_EDGES / 2 + 255) / 256, 256>>>(pos, eidx);
    node_kernel<<<(N_NODES + 255) / 256, 256>>>(bout, gamma, beta, out);
}

// round 8
// speedup vs baseline: 2.0331x; 2.0331x over previous
#include <cuda_runtime.h>
#include <cstdint>

#define N_NODES 100000
#define N_EDGES 500000
#define HIDDEN 32
#define HEADS 4
#define PROJ 128
#define LN_EPS 1e-5f

// Per-node accumulator: [node][head][{Sx,Sy,Sz,T}] = 16 floats. 6.4 MB, L2-hot.
__device__ float g_acc[(size_t)N_NODES * 16];
__device__ int   g_idx64;            // 1 if edge_index is int64
__device__ float g_PJ[HIDDEN * 16];  // folded Wv@Wout (+bv@Wout): [j][h*4+{x,y,z,T}]
__device__ float g_score[HEADS * 13];// per head: M[9] row-major, L[3], C

// ---------------------------------------------------------------------------
// Setup: ONE WARP PER COEFFICIENT (32-length dot products, lane-parallel,
// shfl-reduced). 565 warps over 71 blocks; all loads issue concurrently.
//  warp 0..511   : PJ[j][k]   (j=w>>4, k=w&15, h=k>>2, comp=k&3)
//  warp 512..547 : M[h][i][jj]
//  warp 548..559 : L[h][i]
//  warp 560..563 : C[h]
//  warp 564      : dtype sniff
// ---------------------------------------------------------------------------
__global__ __launch_bounds__(256) void setup_kernel(
    const int* __restrict__ e32,
    const float* __restrict__ Wq, const float* __restrict__ bq,
    const float* __restrict__ Wk, const float* __restrict__ bk,
    const float* __restrict__ Wv, const float* __restrict__ bv,
    const float* __restrict__ Wout)
{
    const int w = blockIdx.x * 8 + (threadIdx.x >> 5);
    const int d = threadIdx.x & 31;

    if (w < 512) {
        const int j = w >> 4, k = w & 15, h = k >> 2, comp = k & 3;
        const int c = h * 32 + d;
        const float a = (comp < 3) ? Wv[comp * PROJ + c] : bv[c];
        float s = a * Wout[c * HIDDEN + j];
#pragma unroll
        for (int off = 16; off; off >>= 1) s += __shfl_xor_sync(0xFFFFFFFFu, s, off);
        if (d == 0) g_PJ[j * 16 + k] = s;
    } else if (w < 548) {
        const int u = w - 512, h = u / 9, ij = u % 9, i = ij / 3, jj = ij % 3;
        const int c = h * 32 + d;
        float s = Wq[i * PROJ + c] * Wk[jj * PROJ + c];
#pragma unroll
        for (int off = 16; off; off >>= 1) s += __shfl_xor_sync(0xFFFFFFFFu, s, off);
        if (d == 0) g_score[h * 13 + ij] = s;
    } else if (w < 560) {
        const int u = w - 548, h = u / 3, i = u % 3;
        const int c = h * 32 + d;
        float s = Wq[i * PROJ + c] * bk[c] + bq[c] * Wk[i * PROJ + c];
#pragma unroll
        for (int off = 16; off; off >>= 1) s += __shfl_xor_sync(0xFFFFFFFFu, s, off);
        if (d == 0) g_score[h * 13 + 9 + i] = s;
    } else if (w < 564) {
        const int h = w - 560;
        const int c = h * 32 + d;
        float s = bq[c] * bk[c];
#pragma unroll
        for (int off = 16; off; off >>= 1) s += __shfl_xor_sync(0xFFFFFFFFu, s, off);
        if (d == 0) g_score[h * 13 + 12] = s;
    } else if (w == 564) {
        // int64 iff the first 64 odd 32-bit words are all zero
        const bool z = (e32[2 * d + 1] == 0) && (e32[2 * (d + 32) + 1] == 0);
        const int all = __all_sync(0xFFFFFFFFu, z);
        if (d == 0) g_idx64 = all;
    }
}

// ---------------------------------------------------------------------------
// Zero the 6.4 MB accumulator.
// ---------------------------------------------------------------------------
__global__ __launch_bounds__(256) void zero_kernel() {
    const size_t n4 = ((size_t)N_NODES * 16) / 4;
    float4* a4 = reinterpret_cast<float4*>(g_acc);
    const size_t stride = (size_t)gridDim.x * blockDim.x;
    for (size_t i = (size_t)blockIdx.x * blockDim.x + threadIdx.x; i < n4; i += stride)
        a4[i] = make_float4(0.f, 0.f, 0.f, 0.f);
}

// ---------------------------------------------------------------------------
// Edge kernel (R6 form, known 19.5us): one thread per edge. Quadratic-form
// scores, 4-way softmax in registers, 4x red.v4.f32 per edge.
// ---------------------------------------------------------------------------
__global__ __launch_bounds__(256) void edge_kernel(
    const float* __restrict__ pos, const void* __restrict__ eidx_raw)
{
    __shared__ float sc[HEADS * 13];
    const int tid = threadIdx.x;
    if (tid < HEADS * 13) sc[tid] = g_score[tid];
    __syncthreads();

    const int e = blockIdx.x * 256 + tid;
    if (e >= N_EDGES) return;

    int row, col;
    if (g_idx64) {
        const long long* p = (const long long*)eidx_raw;
        row = (int)p[e];
        col = (int)p[N_EDGES + e];
    } else {
        const int* p = (const int*)eidx_raw;
        row = p[e];
        col = p[N_EDGES + e];
    }
    if ((unsigned)row >= N_NODES || (unsigned)col >= N_NODES) return;

    const float rx = pos[row * 3 + 0] - pos[col * 3 + 0];
    const float ry = pos[row * 3 + 1] - pos[col * 3 + 1];
    const float rz = pos[row * 3 + 2] - pos[col * 3 + 2];

    float s[HEADS];
#pragma unroll
    for (int h = 0; h < HEADS; h++) {
        const float* m = &sc[h * 13];
        const float tx = fmaf(m[0], rx, fmaf(m[1], ry, m[2] * rz));
        const float ty = fmaf(m[3], rx, fmaf(m[4], ry, m[5] * rz));
        const float tz = fmaf(m[6], rx, fmaf(m[7], ry, m[8] * rz));
        float v = fmaf(rx, tx, fmaf(ry, ty, rz * tz));
        v += fmaf(m[9], rx, fmaf(m[10], ry, fmaf(m[11], rz, m[12])));
        s[h] = v * 0.17677669529663687f;   // 1/sqrt(32)
    }
    const float mx = fmaxf(fmaxf(s[0], s[1]), fmaxf(s[2], s[3]));
    float ex[HEADS], tot = 0.f;
#pragma unroll
    for (int h = 0; h < HEADS; h++) { ex[h] = __expf(s[h] - mx); tot += ex[h]; }
    const float inv = 1.f / tot;

    float* dst = g_acc + (size_t)col * 16;
#pragma unroll
    for (int h = 0; h < HEADS; h++) {
        const float a = ex[h] * inv;
        asm volatile("red.global.add.v4.f32 [%0], {%1,%2,%3,%4};"
                     :: "l"(dst + h * 4), "f"(a * rx), "f"(a * ry), "f"(a * rz), "f"(a)
                     : "memory");
    }
}

// ---------------------------------------------------------------------------
// Node kernel (R6 form): one THREAD per node. 16-float load, 32 outputs via
// folded tables, in-register LayerNorm + SiLU.
// ---------------------------------------------------------------------------
__global__ __launch_bounds__(256) void node_kernel(
    const float* __restrict__ bout, const float* __restrict__ gamma,
    const float* __restrict__ beta, float* __restrict__ out)
{
    __shared__ float sPJ[HIDDEN * 16];
    __shared__ float sb[HIDDEN], sg[HIDDEN], sbt[HIDDEN];
    const int tid = threadIdx.x;
    for (int i = tid; i < HIDDEN * 16; i += 256) sPJ[i] = g_PJ[i];
    if (tid < HIDDEN) { sb[tid] = bout[tid]; sg[tid] = gamma[tid]; sbt[tid] = beta[tid]; }
    __syncthreads();

    const int node = blockIdx.x * 256 + tid;
    if (node >= N_NODES) return;

    const float4* ap = reinterpret_cast<const float4*>(g_acc + (size_t)node * 16);
    const float4 a0 = ap[0], a1 = ap[1], a2 = ap[2], a3 = ap[3];
    const float cnt = a0.w + a1.w + a2.w + a3.w;
    const float inv = 1.f / fmaxf(cnt, 1.f);

    float o[HIDDEN];
    float sum = 0.f;
#pragma unroll
    for (int j = 0; j < HIDDEN; j++) {
        const float4* p = reinterpret_cast<const float4*>(&sPJ[j * 16]);
        const float4 p0 = p[0], p1 = p[1], p2 = p[2], p3 = p[3];
        float d = a0.x * p0.x + a0.y * p0.y + a0.z * p0.z + a0.w * p0.w;
        d += a1.x * p1.x + a1.y * p1.y + a1.z * p1.z + a1.w * p1.w;
        d += a2.x * p2.x + a2.y * p2.y + a2.z * p2.z + a2.w * p2.w;
        d += a3.x * p3.x + a3.y * p3.y + a3.z * p3.z + a3.w * p3.w;
        o[j] = fmaf(d, inv, sb[j]);
        sum += o[j];
    }
    const float mu = sum * (1.f / 32.f);
    float sq = 0.f;
#pragma unroll
    for (int j = 0; j < HIDDEN; j++) { const float d = o[j] - mu; sq += d * d; }
    const float rstd = rsqrtf(sq * (1.f / 32.f) + LN_EPS);

    float4 wreg[8];
#pragma unroll
    for (int j = 0; j < HIDDEN; j++) {
        const float y = (o[j] - mu) * rstd * sg[j] + sbt[j];
        reinterpret_cast<float*>(wreg)[j] = y / (1.f + __expf(-y));
    }
    float4* op = reinterpret_cast<float4*>(out + (size_t)node * HIDDEN);
#pragma unroll
    for (int k = 0; k < 8; k++) op[k] = wreg[k];
}

// ---------------------------------------------------------------------------
extern "C" void kernel_launch(void* const* d_in, const int* in_sizes, int n_in,
                              void* d_out, int out_size)
{
    const float* pos   = (const float*)d_in[0];
    const void*  eidx  = d_in[1];
    const float* Wq    = (const float*)d_in[2];
    const float* bq    = (const float*)d_in[3];
    const float* Wk    = (const float*)d_in[4];
    const float* bk    = (const float*)d_in[5];
    const float* Wv    = (const float*)d_in[6];
    const float* bv    = (const float*)d_in[7];
    const float* Wout  = (const float*)d_in[8];
    const float* bout  = (const float*)d_in[9];
    const float* gamma = (const float*)d_in[10];
    const float* beta  = (const float*)d_in[11];
    float*       out   = (float*)d_out;

    setup_kernel<<<71, 256>>>((const int*)eidx, Wq, bq, Wk, bk, Wv, bv, Wout);
    zero_kernel<<<512, 256>>>();
    edge_kernel<<<(N_EDGES + 255) / 256, 256>>>(pos, eidx);
    node_kernel<<<(N_NODES + 255) / 256, 256>>>(bout, gamma, beta, out);
}